// round 16
// baseline (speedup 1.0000x reference)
#include <cuda_runtime.h>
#include <cuda_fp16.h>

#define NN   50000
#define EE   1600000
#define DIN  128
#define KHOP 8
#define DCAT 1152   // 128*9
#define HID  512
#define DOUT 64

// ------------------------- device scratch (no mallocs allowed) -------------
__device__ int    g_cnt[NN];
__device__ int    g_cursor[NN];
__device__ int    g_offs[NN];
__device__ int    g_bsum[64];
__device__ int    g_is32;                      // 1 = edge_index stored as int32
__device__ float  g_dinv[NN];
__device__ int2   g_edge[EE];                  // packed (src, norm bits)
__device__ __half g_xh[(size_t)NN * DCAT];     // fp16 x (prop state + GEMM1 A) ~115 MB
__device__ __half g_w1t[(size_t)HID * DCAT];   // W1 transposed [N][K] fp16
__device__ __half g_h[(size_t)NN * HID];       // fp16 h (~51 MB)
__device__ float  g_sum[HID];
__device__ float  g_sumsq[HID];
__device__ __half g_W2h[DOUT * HID];           // BN-folded W2^T fp16 [n][k]
__device__ float  g_b2p[DOUT];

// ------------------------------- setup kernels -----------------------------
// zero + dtype probe fused: block 0 probes edge dtype, all blocks zero state.
__global__ void init_kernel(const unsigned int* __restrict__ w) {
    int g = blockIdx.x * blockDim.x + threadIdx.x;
    int stride = gridDim.x * blockDim.x;
    for (int i = g; i < NN; i += stride) { g_cnt[i] = 0; g_cursor[i] = 0; }
    if (g < HID) { g_sum[g] = 0.f; g_sumsq[g] = 0.f; }
    if (blockIdx.x == 0) {
        __shared__ unsigned int sh;
        if (threadIdx.x == 0) sh = 0u;
        __syncthreads();
        unsigned int acc = 0u;
        for (int i = threadIdx.x; i < 8192; i += blockDim.x)
            acc |= w[2 * i + 1];      // odd words of int64 interpretation
        if (acc) atomicOr(&sh, 1u);
        __syncthreads();
        if (threadIdx.x == 0) g_is32 = (sh != 0u) ? 1 : 0;
    }
}

// count in-degrees only (row side decoded later in scatter)
__global__ void convert_kernel(const void* __restrict__ eiv) {
    int e = blockIdx.x * blockDim.x + threadIdx.x;
    if (e >= EE) return;
    int c;
    if (g_is32) {
        c = ((const int*)eiv)[EE + e];
    } else {
        c = (int)((const long long*)eiv)[(size_t)EE + e];
    }
    c = min(max(c, 0), NN - 1);
    atomicAdd(&g_cnt[c], 1);
}

// exclusive scan of g_cnt -> g_offs; also computes dinv + self-loop norms
__global__ void scan_local(float* __restrict__ norm_out) {
    __shared__ int sh[1024];
    int g = blockIdx.x * 1024 + threadIdx.x;
    int v = (g < NN) ? g_cnt[g] : 0;
    if (g < NN) {
        float d = rsqrtf((float)(v + 1));   // +1 self-loop
        g_dinv[g] = d;
        norm_out[(size_t)EE + g] = d * d;
    }
    sh[threadIdx.x] = v;
    __syncthreads();
    for (int d = 1; d < 1024; d <<= 1) {
        int add = (threadIdx.x >= d) ? sh[threadIdx.x - d] : 0;
        __syncthreads();
        sh[threadIdx.x] += add;
        __syncthreads();
    }
    if (g < NN) g_offs[g] = sh[threadIdx.x] - v;
    if (threadIdx.x == 1023) g_bsum[blockIdx.x] = sh[1023];
}

// warp-parallel exclusive scan of g_bsum (nb <= 64), chunked with carry
__global__ void scan_bsum(int nb) {
    int lane = threadIdx.x;   // 32 threads
    int carry = 0;
    for (int base = 0; base < nb; base += 32) {
        int i = base + lane;
        int v = (i < nb) ? g_bsum[i] : 0;
        int incl = v;
#pragma unroll
        for (int off = 1; off < 32; off <<= 1) {
            int n = __shfl_up_sync(0xffffffffu, incl, off);
            if (lane >= off) incl += n;
        }
        if (i < nb) g_bsum[i] = incl - v + carry;
        carry += __shfl_sync(0xffffffffu, incl, 31);
    }
}

__global__ void scan_add() {
    int g = blockIdx.x * 1024 + threadIdx.x;
    if (g < NN) g_offs[g] += g_bsum[blockIdx.x];
}

// scatter: re-decodes edges, computes norms, packs (src, norm) records
__global__ void scatter_kernel(const void* __restrict__ eiv, float* __restrict__ norm_out) {
    int e = blockIdx.x * blockDim.x + threadIdx.x;
    if (e >= EE) return;
    int r, c;
    if (g_is32) {
        const int* ei = (const int*)eiv;
        r = ei[e];
        c = ei[EE + e];
    } else {
        const long long* ei = (const long long*)eiv;
        r = (int)ei[e];
        c = (int)ei[(size_t)EE + e];
    }
    r = min(max(r, 0), NN - 1);
    c = min(max(c, 0), NN - 1);
    float nv = g_dinv[r] * g_dinv[c];
    norm_out[e] = nv;
    int p = g_offs[c] + atomicAdd(&g_cursor[c], 1);
    g_edge[p] = make_int2(r, __float_as_int(nv));
}

__global__ void copy_x0(const float* __restrict__ feat) {
    int idx = blockIdx.x * blockDim.x + threadIdx.x;
    if (idx >= NN * DIN / 2) return;
    int i = idx / (DIN / 2);
    int j = idx % (DIN / 2);
    float2 v = *(const float2*)(feat + (size_t)i * DIN + j * 2);
    __half2 h = __floats2half2_rn(v.x, v.y);
    *(__half2*)(g_xh + (size_t)i * DCAT + j * 2) = h;
}

// transpose W1 [K][N] fp32 -> W1T [N][K] fp16 (tiled, coalesced both sides)
__global__ void w1t_kernel(const float* __restrict__ W1) {
    __shared__ float sh[32][33];
    int k0 = blockIdx.x * 32;
    int n0 = blockIdx.y * 32;
    int tx = threadIdx.x, ty = threadIdx.y;
    sh[ty][tx] = W1[(size_t)(k0 + ty) * HID + n0 + tx];
    __syncthreads();
    g_w1t[(size_t)(n0 + ty) * DCAT + k0 + tx] = __float2half(sh[tx][ty]);
}

// ---------- propagation (TWO warps per node: 64 halves = 128B each) --------
// Doubles independent gather streams vs one warp/node; per-gather request is
// one 128B line. Edge records are re-read by both warps (L2 broadcast).
__global__ void prop_kernel(int kb_in, int kb_out) {
    int gw = (blockIdx.x * blockDim.x + threadIdx.x) >> 5;
    int lane = threadIdx.x & 31;
    int node = gw >> 1;
    int half = gw & 1;
    if (node >= NN) return;
    int fo = half * 64 + lane * 2;   // 2 halves per lane
    float d = g_dinv[node];
    float w0 = d * d;
    unsigned sv = *(const unsigned*)(g_xh + (size_t)node * DCAT + kb_in + fo);
    float2 s0 = __half22float2(*(__half2*)&sv);
    float2 acc = make_float2(w0 * s0.x, w0 * s0.y);
    int start = g_offs[node];
    int end = start + g_cnt[node];
#pragma unroll 8
    for (int e = start; e < end; e++) {
        int2 er = g_edge[e];
        float w = __int_as_float(er.y);
        unsigned uv = *(const unsigned*)(g_xh + (size_t)er.x * DCAT + kb_in + fo);
        float2 f0 = __half22float2(*(__half2*)&uv);
        acc.x += w * f0.x;
        acc.y += w * f0.y;
    }
    __half2 o0 = __floats2half2_rn(acc.x, acc.y);
    *(unsigned*)(g_xh + (size_t)node * DCAT + kb_out + fo) = *(unsigned*)&o0;
}

// ------------------- GEMM1 (fp16 tensor cores): h = lrelu(X@W1+b1) ---------
// A = g_xh [NN][DCAT] fp16, B = g_w1t [HID][DCAT] fp16 (W1^T K-major).
// Block 128x128, K-step 16, mma.m16n8k16, scalar-LDS fragments (proven).
// 3-stage cp.async pipeline. Epilogue accumulates BN stats (R14-proven).

#define HSTR 24
#define KTILES (DCAT / 16)   // 72

__device__ __forceinline__ void cpa16(unsigned saddr, const void* gptr, int srcbytes) {
    asm volatile("cp.async.cg.shared.global [%0], [%1], 16, %2;"
                 :: "r"(saddr), "l"(gptr), "r"(srcbytes));
}
__device__ __forceinline__ void cpa_commit() {
    asm volatile("cp.async.commit_group;");
}
template <int N>
__device__ __forceinline__ void cpa_wait() {
    asm volatile("cp.async.wait_group %0;" :: "n"(N));
}

__global__ __launch_bounds__(256) void gemm1_fp16_kernel(const float* __restrict__ b1) {
    __shared__ __align__(16) __half As[3][128][HSTR];   // [stage][m][k]
    __shared__ __align__(16) __half Bs[3][128][HSTR];   // [stage][n][k]

    int bm = blockIdx.y * 128;
    int bn = blockIdx.x * 128;
    int tid = threadIdx.x;
    int lane = tid & 31;
    int wid = tid >> 5;
    int warp_m = wid & 3;      // m offset 32*warp_m
    int warp_n = wid >> 2;     // n offset 64*warp_n

    int grow = tid >> 1;            // 0..127
    int gkoff = (tid & 1) * 8;      // 0 or 8

    int ar = bm + grow;
    int aval = (ar < NN) ? 16 : 0;                 // zfill OOB rows
    const __half* agp = g_xh + (size_t)min(ar, NN - 1) * DCAT + gkoff;
    const __half* bgp = g_w1t + (size_t)(bn + grow) * DCAT + gkoff;
    unsigned asm_base = (unsigned)__cvta_generic_to_shared(&As[0][grow][gkoff]);
    unsigned bsm_base = (unsigned)__cvta_generic_to_shared(&Bs[0][grow][gkoff]);
    const unsigned stageB = 128 * HSTR * 2;        // bytes per stage

    float acc[2][8][4];
#pragma unroll
    for (int mi = 0; mi < 2; mi++)
#pragma unroll
        for (int ni = 0; ni < 8; ni++)
#pragma unroll
            for (int j = 0; j < 4; j++) acc[mi][ni][j] = 0.f;

    // prologue: stages 0 and 1
#pragma unroll
    for (int s = 0; s < 2; s++) {
        cpa16(asm_base + s * stageB, agp + s * 16, aval);
        cpa16(bsm_base + s * stageB, bgp + s * 16, 16);
        cpa_commit();
    }

    int stage = 0;
    for (int kt = 0; kt < KTILES; kt++) {
        cpa_wait<1>();          // stage kt landed
        __syncthreads();

        if (kt + 2 < KTILES) {
            int s2 = (kt + 2) % 3;
            cpa16(asm_base + s2 * stageB, agp + (kt + 2) * 16, aval);
            cpa16(bsm_base + s2 * stageB, bgp + (kt + 2) * 16, 16);
        }
        cpa_commit();           // keep group count in lockstep every iter

        int mg = lane >> 2;
        int tk = (lane & 3) * 2;
        unsigned afrag[2][4], bfrag[8][2];
#pragma unroll
        for (int mi = 0; mi < 2; mi++) {
            int m0 = warp_m * 32 + mi * 16 + mg;
            afrag[mi][0] = *(const unsigned*)&As[stage][m0][tk];
            afrag[mi][1] = *(const unsigned*)&As[stage][m0 + 8][tk];
            afrag[mi][2] = *(const unsigned*)&As[stage][m0][tk + 8];
            afrag[mi][3] = *(const unsigned*)&As[stage][m0 + 8][tk + 8];
        }
#pragma unroll
        for (int ni = 0; ni < 8; ni++) {
            int n0 = warp_n * 64 + ni * 8 + mg;
            bfrag[ni][0] = *(const unsigned*)&Bs[stage][n0][tk];
            bfrag[ni][1] = *(const unsigned*)&Bs[stage][n0][tk + 8];
        }
#pragma unroll
        for (int mi = 0; mi < 2; mi++)
#pragma unroll
            for (int ni = 0; ni < 8; ni++) {
                asm volatile(
                    "mma.sync.aligned.m16n8k16.row.col.f32.f16.f16.f32 "
                    "{%0,%1,%2,%3}, {%4,%5,%6,%7}, {%8,%9}, {%0,%1,%2,%3};"
                    : "+f"(acc[mi][ni][0]), "+f"(acc[mi][ni][1]),
                      "+f"(acc[mi][ni][2]), "+f"(acc[mi][ni][3])
                    : "r"(afrag[mi][0]), "r"(afrag[mi][1]),
                      "r"(afrag[mi][2]), "r"(afrag[mi][3]),
                      "r"(bfrag[ni][0]), "r"(bfrag[ni][1]));
            }
        stage = (stage + 1) % 3;
        // buffer reuse safety: stage kt's buffer is rewritten when iteration
        // kt+1 issues stage kt+3 — after the barrier that all warps reach only
        // once they finished computing stage kt.
    }

    // epilogue: bias + leaky relu, write h (fp16), accumulate BN stats
    int mg = lane >> 2;
    int cq = (lane & 3) * 2;
#pragma unroll
    for (int ni = 0; ni < 8; ni++) {
        int c = bn + warp_n * 64 + ni * 8 + cq;
        float bb0 = b1[c], bb1 = b1[c + 1];
        float s0 = 0.f, s1 = 0.f, q0 = 0.f, q1 = 0.f;
#pragma unroll
        for (int mi = 0; mi < 2; mi++) {
            int r0 = bm + warp_m * 32 + mi * 16 + mg;
            float v0 = acc[mi][ni][0] + bb0;
            float v1 = acc[mi][ni][1] + bb1;
            float v2 = acc[mi][ni][2] + bb0;
            float v3 = acc[mi][ni][3] + bb1;
            v0 = v0 > 0.f ? v0 : 0.2f * v0;
            v1 = v1 > 0.f ? v1 : 0.2f * v1;
            v2 = v2 > 0.f ? v2 : 0.2f * v2;
            v3 = v3 > 0.f ? v3 : 0.2f * v3;
            if (r0 < NN) {
                *(__half2*)(g_h + (size_t)r0 * HID + c) = __floats2half2_rn(v0, v1);
                s0 += v0; s1 += v1; q0 += v0 * v0; q1 += v1 * v1;
            }
            if (r0 + 8 < NN) {
                *(__half2*)(g_h + (size_t)(r0 + 8) * HID + c) = __floats2half2_rn(v2, v3);
                s0 += v2; s1 += v3; q0 += v2 * v2; q1 += v3 * v3;
            }
        }
        // reduce across the 8 m-groups (lane bits 2..4)
#pragma unroll
        for (int off = 4; off <= 16; off <<= 1) {
            s0 += __shfl_xor_sync(0xffffffffu, s0, off);
            s1 += __shfl_xor_sync(0xffffffffu, s1, off);
            q0 += __shfl_xor_sync(0xffffffffu, q0, off);
            q1 += __shfl_xor_sync(0xffffffffu, q1, off);
        }
        if (mg == 0) {
            atomicAdd(&g_sum[c], s0);
            atomicAdd(&g_sum[c + 1], s1);
            atomicAdd(&g_sumsq[c], q0);
            atomicAdd(&g_sumsq[c + 1], q1);
        }
    }
}

// fold BN into W2h (fp16, transposed [n][k]) and b2p
__global__ void finalize_kernel(const float* __restrict__ W2, const float* __restrict__ b2,
                                const float* __restrict__ gamma, const float* __restrict__ beta) {
    __shared__ float ss[HID], st[HID];
    int t = threadIdx.x;   // 512
    float mean = g_sum[t] * (1.0f / NN);
    float var  = g_sumsq[t] * (1.0f / NN) - mean * mean;
    float rstd = rsqrtf(var + 1e-5f);
    float sc = gamma[t] * rstd;
    ss[t] = sc;
    st[t] = beta[t] - mean * sc;
    __syncthreads();
    for (int idx = t; idx < HID * DOUT; idx += 512) {
        int k = idx >> 6;        // W2 is [k][n]
        int n = idx & 63;
        g_W2h[n * HID + k] = __float2half(ss[k] * W2[idx]);
    }
    if (t < DOUT) {
        float acc = b2[t];
        for (int k = 0; k < HID; k++)
            acc += st[k] * W2[k * DOUT + t];
        g_b2p[t] = acc;
    }
}

// ---------------- GEMM2 (fp16 tensor cores): out = h@W2' + b2' -------------
// A = g_h [NN][HID] fp16, B = g_W2h [64][HID] fp16 (K-major).
// Block 128m x 64n, K-step 16, 8 warps 4(m) x 2(n); warp tile 32x32.
#define K2TILES (HID / 16)   // 32

__global__ __launch_bounds__(256) void gemm2_fp16_kernel(float* __restrict__ out) {
    __shared__ __align__(16) __half As[2][128][HSTR];
    __shared__ __align__(16) __half Bs[2][64][HSTR];

    int bm = blockIdx.x * 128;
    int tid = threadIdx.x;
    int lane = tid & 31;
    int wid = tid >> 5;
    int warp_m = wid & 3;      // m offset 32*warp_m
    int warp_n = wid >> 2;     // n offset 32*warp_n

    int grow = tid >> 1;            // 0..127
    int gkoff = (tid & 1) * 8;      // 0 or 8

    float acc[2][4][4];
#pragma unroll
    for (int mi = 0; mi < 2; mi++)
#pragma unroll
        for (int ni = 0; ni < 4; ni++)
#pragma unroll
            for (int j = 0; j < 4; j++) acc[mi][ni][j] = 0.f;

    uint4 ra, rb;
    {
        int r = bm + grow;
        ra = make_uint4(0, 0, 0, 0);
        if (r < NN) ra = *(const uint4*)(g_h + (size_t)r * HID + gkoff);
        rb = make_uint4(0, 0, 0, 0);
        if (grow < 64) rb = *(const uint4*)(g_W2h + (size_t)grow * HID + gkoff);
    }

    for (int kt = 0; kt < K2TILES; kt++) {
        int buf = kt & 1;
        *(uint4*)&As[buf][grow][gkoff] = ra;
        if (grow < 64) *(uint4*)&Bs[buf][grow][gkoff] = rb;
        __syncthreads();

        if (kt + 1 < K2TILES) {
            int k0 = (kt + 1) * 16;
            int r = bm + grow;
            ra = make_uint4(0, 0, 0, 0);
            if (r < NN) ra = *(const uint4*)(g_h + (size_t)r * HID + k0 + gkoff);
            if (grow < 64) rb = *(const uint4*)(g_W2h + (size_t)grow * HID + k0 + gkoff);
        }

        int mg = lane >> 2;
        int tk = (lane & 3) * 2;
        unsigned afrag[2][4], bfrag[4][2];
#pragma unroll
        for (int mi = 0; mi < 2; mi++) {
            int m0 = warp_m * 32 + mi * 16 + mg;
            afrag[mi][0] = *(const unsigned*)&As[buf][m0][tk];
            afrag[mi][1] = *(const unsigned*)&As[buf][m0 + 8][tk];
            afrag[mi][2] = *(const unsigned*)&As[buf][m0][tk + 8];
            afrag[mi][3] = *(const unsigned*)&As[buf][m0 + 8][tk + 8];
        }
#pragma unroll
        for (int ni = 0; ni < 4; ni++) {
            int n0 = warp_n * 32 + ni * 8 + mg;
            bfrag[ni][0] = *(const unsigned*)&Bs[buf][n0][tk];
            bfrag[ni][1] = *(const unsigned*)&Bs[buf][n0][tk + 8];
        }
#pragma unroll
        for (int mi = 0; mi < 2; mi++)
#pragma unroll
            for (int ni = 0; ni < 4; ni++) {
                asm volatile(
                    "mma.sync.aligned.m16n8k16.row.col.f32.f16.f16.f32 "
                    "{%0,%1,%2,%3}, {%4,%5,%6,%7}, {%8,%9}, {%0,%1,%2,%3};"
                    : "+f"(acc[mi][ni][0]), "+f"(acc[mi][ni][1]),
                      "+f"(acc[mi][ni][2]), "+f"(acc[mi][ni][3])
                    : "r"(afrag[mi][0]), "r"(afrag[mi][1]),
                      "r"(afrag[mi][2]), "r"(afrag[mi][3]),
                      "r"(bfrag[ni][0]), "r"(bfrag[ni][1]));
            }
    }

    // epilogue: add folded bias, write fp32 out
    int mg = lane >> 2;
    int cq = (lane & 3) * 2;
#pragma unroll
    for (int mi = 0; mi < 2; mi++) {
        int r0 = bm + warp_m * 32 + mi * 16 + mg;
#pragma unroll
        for (int ni = 0; ni < 4; ni++) {
            int c = warp_n * 32 + ni * 8 + cq;
            float bb0 = g_b2p[c], bb1 = g_b2p[c + 1];
            if (r0 < NN)
                *(float2*)(out + (size_t)r0 * DOUT + c) =
                    make_float2(acc[mi][ni][0] + bb0, acc[mi][ni][1] + bb1);
            if (r0 + 8 < NN)
                *(float2*)(out + (size_t)(r0 + 8) * DOUT + c) =
                    make_float2(acc[mi][ni][2] + bb0, acc[mi][ni][3] + bb1);
        }
    }
}

// --------------------------------- launch ----------------------------------
extern "C" void kernel_launch(void* const* d_in, const int* in_sizes, int n_in,
                              void* d_out, int out_size) {
    const float* feat  = (const float*)d_in[0];
    const void*  ei    = d_in[1];
    const float* W1    = (const float*)d_in[2];
    const float* b1    = (const float*)d_in[3];
    const float* gamma = (const float*)d_in[4];
    const float* beta  = (const float*)d_in[5];
    const float* W2    = (const float*)d_in[6];
    const float* b2    = (const float*)d_in[7];
    float* out = (float*)d_out;
    float* norm_out = out + (size_t)NN * DOUT;   // [E+N] norm output section

    init_kernel<<<128, 512>>>((const unsigned int*)ei);
    convert_kernel<<<(EE + 255) / 256, 256>>>(ei);

    int nb = (NN + 1023) / 1024;   // 49
    scan_local<<<nb, 1024>>>(norm_out);
    scan_bsum<<<1, 32>>>(nb);
    scan_add<<<nb, 1024>>>();
    scatter_kernel<<<(EE + 255) / 256, 256>>>(ei, norm_out);

    copy_x0<<<(NN * DIN / 2 + 255) / 256, 256>>>(feat);
    w1t_kernel<<<dim3(DCAT / 32, HID / 32), dim3(32, 32)>>>(W1);

    for (int k = 0; k < KHOP; k++)
        prop_kernel<<<(NN * 64 + 255) / 256, 256>>>(k * DIN, (k + 1) * DIN);

    dim3 g1(HID / 128, (NN + 127) / 128);
    gemm1_fp16_kernel<<<g1, 256>>>(b1);

    finalize_kernel<<<1, 512>>>(W2, b2, gamma, beta);

    gemm2_fp16_kernel<<<(NN + 127) / 128, 256>>>(out);
}

// round 17
// speedup vs baseline: 1.1418x; 1.1418x over previous
#include <cuda_runtime.h>
#include <cuda_fp16.h>

#define NN   50000
#define EE   1600000
#define DIN  128
#define KHOP 8
#define DCAT 1152   // 128*9
#define HID  512
#define DOUT 64

// ------------------------- device scratch (no mallocs allowed) -------------
__device__ int    g_cnt[NN];
__device__ int    g_cursor[NN];
__device__ int    g_offs[NN];
__device__ int    g_bsum[64];
__device__ int    g_is32;                      // 1 = edge_index stored as int32
__device__ float  g_dinv[NN];
__device__ int2   g_edge[EE];                  // packed (src, norm bits)
__device__ __half g_xh[(size_t)NN * DCAT];     // fp16 x (prop state + GEMM1 A) ~115 MB
__device__ __half g_w1t[(size_t)HID * DCAT];   // W1 transposed [N][K] fp16
__device__ __half g_h[(size_t)NN * HID];       // fp16 h (~51 MB)
__device__ float  g_sum[HID];
__device__ float  g_sumsq[HID];
__device__ __half g_W2h[DOUT * HID];           // BN-folded W2^T fp16 [n][k]
__device__ float  g_b2p[DOUT];

// ------------------------------- setup kernels -----------------------------
// zero + dtype probe fused: block 0 probes edge dtype, all blocks zero state.
__global__ void init_kernel(const unsigned int* __restrict__ w) {
    int g = blockIdx.x * blockDim.x + threadIdx.x;
    int stride = gridDim.x * blockDim.x;
    for (int i = g; i < NN; i += stride) { g_cnt[i] = 0; g_cursor[i] = 0; }
    if (g < HID) { g_sum[g] = 0.f; g_sumsq[g] = 0.f; }
    if (blockIdx.x == 0) {
        __shared__ unsigned int sh;
        if (threadIdx.x == 0) sh = 0u;
        __syncthreads();
        unsigned int acc = 0u;
        for (int i = threadIdx.x; i < 8192; i += blockDim.x)
            acc |= w[2 * i + 1];      // odd words of int64 interpretation
        if (acc) atomicOr(&sh, 1u);
        __syncthreads();
        if (threadIdx.x == 0) g_is32 = (sh != 0u) ? 1 : 0;
    }
}

// count in-degrees only (row side decoded later in scatter)
__global__ void convert_kernel(const void* __restrict__ eiv) {
    int e = blockIdx.x * blockDim.x + threadIdx.x;
    if (e >= EE) return;
    int c;
    if (g_is32) {
        c = ((const int*)eiv)[EE + e];
    } else {
        c = (int)((const long long*)eiv)[(size_t)EE + e];
    }
    c = min(max(c, 0), NN - 1);
    atomicAdd(&g_cnt[c], 1);
}

// exclusive scan of g_cnt -> g_offs; also computes dinv + self-loop norms
__global__ void scan_local(float* __restrict__ norm_out) {
    __shared__ int sh[1024];
    int g = blockIdx.x * 1024 + threadIdx.x;
    int v = (g < NN) ? g_cnt[g] : 0;
    if (g < NN) {
        float d = rsqrtf((float)(v + 1));   // +1 self-loop
        g_dinv[g] = d;
        norm_out[(size_t)EE + g] = d * d;
    }
    sh[threadIdx.x] = v;
    __syncthreads();
    for (int d = 1; d < 1024; d <<= 1) {
        int add = (threadIdx.x >= d) ? sh[threadIdx.x - d] : 0;
        __syncthreads();
        sh[threadIdx.x] += add;
        __syncthreads();
    }
    if (g < NN) g_offs[g] = sh[threadIdx.x] - v;
    if (threadIdx.x == 1023) g_bsum[blockIdx.x] = sh[1023];
}

// warp-parallel exclusive scan of g_bsum (nb <= 64), chunked with carry
__global__ void scan_bsum(int nb) {
    int lane = threadIdx.x;   // 32 threads
    int carry = 0;
    for (int base = 0; base < nb; base += 32) {
        int i = base + lane;
        int v = (i < nb) ? g_bsum[i] : 0;
        int incl = v;
#pragma unroll
        for (int off = 1; off < 32; off <<= 1) {
            int n = __shfl_up_sync(0xffffffffu, incl, off);
            if (lane >= off) incl += n;
        }
        if (i < nb) g_bsum[i] = incl - v + carry;
        carry += __shfl_sync(0xffffffffu, incl, 31);
    }
}

__global__ void scan_add() {
    int g = blockIdx.x * 1024 + threadIdx.x;
    if (g < NN) g_offs[g] += g_bsum[blockIdx.x];
}

// scatter: re-decodes edges, computes norms, packs (src, norm) records
__global__ void scatter_kernel(const void* __restrict__ eiv, float* __restrict__ norm_out) {
    int e = blockIdx.x * blockDim.x + threadIdx.x;
    if (e >= EE) return;
    int r, c;
    if (g_is32) {
        const int* ei = (const int*)eiv;
        r = ei[e];
        c = ei[EE + e];
    } else {
        const long long* ei = (const long long*)eiv;
        r = (int)ei[e];
        c = (int)ei[(size_t)EE + e];
    }
    r = min(max(r, 0), NN - 1);
    c = min(max(c, 0), NN - 1);
    float nv = g_dinv[r] * g_dinv[c];
    norm_out[e] = nv;
    int p = g_offs[c] + atomicAdd(&g_cursor[c], 1);
    g_edge[p] = make_int2(r, __float_as_int(nv));
}

__global__ void copy_x0(const float* __restrict__ feat) {
    int idx = blockIdx.x * blockDim.x + threadIdx.x;
    if (idx >= NN * DIN / 2) return;
    int i = idx / (DIN / 2);
    int j = idx % (DIN / 2);
    float2 v = *(const float2*)(feat + (size_t)i * DIN + j * 2);
    __half2 h = __floats2half2_rn(v.x, v.y);
    *(__half2*)(g_xh + (size_t)i * DCAT + j * 2) = h;
}

// transpose W1 [K][N] fp32 -> W1T [N][K] fp16 (tiled, coalesced both sides)
__global__ void w1t_kernel(const float* __restrict__ W1) {
    __shared__ float sh[32][33];
    int k0 = blockIdx.x * 32;
    int n0 = blockIdx.y * 32;
    int tx = threadIdx.x, ty = threadIdx.y;
    sh[ty][tx] = W1[(size_t)(k0 + ty) * HID + n0 + tx];
    __syncthreads();
    g_w1t[(size_t)(n0 + ty) * DCAT + k0 + tx] = __float2half(sh[tx][ty]);
}

// ------------------- propagation (warp per node, fp16 gather) --------------
__global__ void prop_kernel(int kb_in, int kb_out) {
    int warp = (blockIdx.x * blockDim.x + threadIdx.x) >> 5;
    int lane = threadIdx.x & 31;
    if (warp >= NN) return;
    int fo = lane * 4;   // 4 halves per lane
    float d = g_dinv[warp];
    float w0 = d * d;
    uint2 sv = *(const uint2*)(g_xh + (size_t)warp * DCAT + kb_in + fo);
    float2 s0 = __half22float2(*(__half2*)&sv.x);
    float2 s1 = __half22float2(*(__half2*)&sv.y);
    float4 acc = make_float4(w0 * s0.x, w0 * s0.y, w0 * s1.x, w0 * s1.y);
    int start = g_offs[warp];
    int end = start + g_cnt[warp];
#pragma unroll 8
    for (int e = start; e < end; e++) {
        int2 er = g_edge[e];
        float w = __int_as_float(er.y);
        uint2 uv = *(const uint2*)(g_xh + (size_t)er.x * DCAT + kb_in + fo);
        float2 f0 = __half22float2(*(__half2*)&uv.x);
        float2 f1 = __half22float2(*(__half2*)&uv.y);
        acc.x += w * f0.x;
        acc.y += w * f0.y;
        acc.z += w * f1.x;
        acc.w += w * f1.y;
    }
    __half2 o0 = __floats2half2_rn(acc.x, acc.y);
    __half2 o1 = __floats2half2_rn(acc.z, acc.w);
    *(uint2*)(g_xh + (size_t)warp * DCAT + kb_out + fo) =
        make_uint2(*(unsigned*)&o0, *(unsigned*)&o1);
}

// ------------------- GEMM1 (fp16 tensor cores): h = lrelu(X@W1+b1) ---------
// A = g_xh [NN][DCAT] fp16, B = g_w1t [HID][DCAT] fp16 (W1^T K-major).
// Block 128x128, K-step 16, mma.m16n8k16, scalar-LDS fragments (proven).
// 3-stage cp.async pipeline. Epilogue accumulates BN stats (R14-proven).

#define HSTR 24
#define KTILES (DCAT / 16)   // 72

__device__ __forceinline__ void cpa16(unsigned saddr, const void* gptr, int srcbytes) {
    asm volatile("cp.async.cg.shared.global [%0], [%1], 16, %2;"
                 :: "r"(saddr), "l"(gptr), "r"(srcbytes));
}
__device__ __forceinline__ void cpa_commit() {
    asm volatile("cp.async.commit_group;");
}
template <int N>
__device__ __forceinline__ void cpa_wait() {
    asm volatile("cp.async.wait_group %0;" :: "n"(N));
}

__global__ __launch_bounds__(256) void gemm1_fp16_kernel(const float* __restrict__ b1) {
    __shared__ __align__(16) __half As[3][128][HSTR];   // [stage][m][k]
    __shared__ __align__(16) __half Bs[3][128][HSTR];   // [stage][n][k]

    int bm = blockIdx.y * 128;
    int bn = blockIdx.x * 128;
    int tid = threadIdx.x;
    int lane = tid & 31;
    int wid = tid >> 5;
    int warp_m = wid & 3;      // m offset 32*warp_m
    int warp_n = wid >> 2;     // n offset 64*warp_n

    int grow = tid >> 1;            // 0..127
    int gkoff = (tid & 1) * 8;      // 0 or 8

    int ar = bm + grow;
    int aval = (ar < NN) ? 16 : 0;                 // zfill OOB rows
    const __half* agp = g_xh + (size_t)min(ar, NN - 1) * DCAT + gkoff;
    const __half* bgp = g_w1t + (size_t)(bn + grow) * DCAT + gkoff;
    unsigned asm_base = (unsigned)__cvta_generic_to_shared(&As[0][grow][gkoff]);
    unsigned bsm_base = (unsigned)__cvta_generic_to_shared(&Bs[0][grow][gkoff]);
    const unsigned stageB = 128 * HSTR * 2;        // bytes per stage

    float acc[2][8][4];
#pragma unroll
    for (int mi = 0; mi < 2; mi++)
#pragma unroll
        for (int ni = 0; ni < 8; ni++)
#pragma unroll
            for (int j = 0; j < 4; j++) acc[mi][ni][j] = 0.f;

    // prologue: stages 0 and 1
#pragma unroll
    for (int s = 0; s < 2; s++) {
        cpa16(asm_base + s * stageB, agp + s * 16, aval);
        cpa16(bsm_base + s * stageB, bgp + s * 16, 16);
        cpa_commit();
    }

    int stage = 0;
    for (int kt = 0; kt < KTILES; kt++) {
        cpa_wait<1>();          // stage kt landed
        __syncthreads();

        if (kt + 2 < KTILES) {
            int s2 = (kt + 2) % 3;
            cpa16(asm_base + s2 * stageB, agp + (kt + 2) * 16, aval);
            cpa16(bsm_base + s2 * stageB, bgp + (kt + 2) * 16, 16);
        }
        cpa_commit();           // keep group count in lockstep every iter

        int mg = lane >> 2;
        int tk = (lane & 3) * 2;
        unsigned afrag[2][4], bfrag[8][2];
#pragma unroll
        for (int mi = 0; mi < 2; mi++) {
            int m0 = warp_m * 32 + mi * 16 + mg;
            afrag[mi][0] = *(const unsigned*)&As[stage][m0][tk];
            afrag[mi][1] = *(const unsigned*)&As[stage][m0 + 8][tk];
            afrag[mi][2] = *(const unsigned*)&As[stage][m0][tk + 8];
            afrag[mi][3] = *(const unsigned*)&As[stage][m0 + 8][tk + 8];
        }
#pragma unroll
        for (int ni = 0; ni < 8; ni++) {
            int n0 = warp_n * 64 + ni * 8 + mg;
            bfrag[ni][0] = *(const unsigned*)&Bs[stage][n0][tk];
            bfrag[ni][1] = *(const unsigned*)&Bs[stage][n0][tk + 8];
        }
#pragma unroll
        for (int mi = 0; mi < 2; mi++)
#pragma unroll
            for (int ni = 0; ni < 8; ni++) {
                asm volatile(
                    "mma.sync.aligned.m16n8k16.row.col.f32.f16.f16.f32 "
                    "{%0,%1,%2,%3}, {%4,%5,%6,%7}, {%8,%9}, {%0,%1,%2,%3};"
                    : "+f"(acc[mi][ni][0]), "+f"(acc[mi][ni][1]),
                      "+f"(acc[mi][ni][2]), "+f"(acc[mi][ni][3])
                    : "r"(afrag[mi][0]), "r"(afrag[mi][1]),
                      "r"(afrag[mi][2]), "r"(afrag[mi][3]),
                      "r"(bfrag[ni][0]), "r"(bfrag[ni][1]));
            }
        stage = (stage + 1) % 3;
        // buffer reuse safety: stage kt's buffer is rewritten when iteration
        // kt+1 issues stage kt+3 — after the barrier that all warps reach only
        // once they finished computing stage kt.
    }

    // epilogue: bias + leaky relu, write h (fp16), accumulate BN stats
    int mg = lane >> 2;
    int cq = (lane & 3) * 2;
#pragma unroll
    for (int ni = 0; ni < 8; ni++) {
        int c = bn + warp_n * 64 + ni * 8 + cq;
        float bb0 = b1[c], bb1 = b1[c + 1];
        float s0 = 0.f, s1 = 0.f, q0 = 0.f, q1 = 0.f;
#pragma unroll
        for (int mi = 0; mi < 2; mi++) {
            int r0 = bm + warp_m * 32 + mi * 16 + mg;
            float v0 = acc[mi][ni][0] + bb0;
            float v1 = acc[mi][ni][1] + bb1;
            float v2 = acc[mi][ni][2] + bb0;
            float v3 = acc[mi][ni][3] + bb1;
            v0 = v0 > 0.f ? v0 : 0.2f * v0;
            v1 = v1 > 0.f ? v1 : 0.2f * v1;
            v2 = v2 > 0.f ? v2 : 0.2f * v2;
            v3 = v3 > 0.f ? v3 : 0.2f * v3;
            if (r0 < NN) {
                *(__half2*)(g_h + (size_t)r0 * HID + c) = __floats2half2_rn(v0, v1);
                s0 += v0; s1 += v1; q0 += v0 * v0; q1 += v1 * v1;
            }
            if (r0 + 8 < NN) {
                *(__half2*)(g_h + (size_t)(r0 + 8) * HID + c) = __floats2half2_rn(v2, v3);
                s0 += v2; s1 += v3; q0 += v2 * v2; q1 += v3 * v3;
            }
        }
        // reduce across the 8 m-groups (lane bits 2..4)
#pragma unroll
        for (int off = 4; off <= 16; off <<= 1) {
            s0 += __shfl_xor_sync(0xffffffffu, s0, off);
            s1 += __shfl_xor_sync(0xffffffffu, s1, off);
            q0 += __shfl_xor_sync(0xffffffffu, q0, off);
            q1 += __shfl_xor_sync(0xffffffffu, q1, off);
        }
        if (mg == 0) {
            atomicAdd(&g_sum[c], s0);
            atomicAdd(&g_sum[c + 1], s1);
            atomicAdd(&g_sumsq[c], q0);
            atomicAdd(&g_sumsq[c + 1], q1);
        }
    }
}

// fold BN into W2h (fp16, transposed [n][k]) and b2p
__global__ void finalize_kernel(const float* __restrict__ W2, const float* __restrict__ b2,
                                const float* __restrict__ gamma, const float* __restrict__ beta) {
    __shared__ float ss[HID], st[HID];
    int t = threadIdx.x;   // 512
    float mean = g_sum[t] * (1.0f / NN);
    float var  = g_sumsq[t] * (1.0f / NN) - mean * mean;
    float rstd = rsqrtf(var + 1e-5f);
    float sc = gamma[t] * rstd;
    ss[t] = sc;
    st[t] = beta[t] - mean * sc;
    __syncthreads();
    for (int idx = t; idx < HID * DOUT; idx += 512) {
        int k = idx >> 6;        // W2 is [k][n]
        int n = idx & 63;
        g_W2h[n * HID + k] = __float2half(ss[k] * W2[idx]);
    }
    if (t < DOUT) {
        float acc = b2[t];
        for (int k = 0; k < HID; k++)
            acc += st[k] * W2[k * DOUT + t];
        g_b2p[t] = acc;
    }
}

// ---------------- GEMM2 (fp16 tensor cores): out = h@W2' + b2' -------------
// A = g_h [NN][HID] fp16, B = g_W2h [64][HID] fp16 (K-major).
// Block 128m x 64n, K-step 16, 8 warps 4(m) x 2(n); warp tile 32x32.
#define K2TILES (HID / 16)   // 32

__global__ __launch_bounds__(256) void gemm2_fp16_kernel(float* __restrict__ out) {
    __shared__ __align__(16) __half As[2][128][HSTR];
    __shared__ __align__(16) __half Bs[2][64][HSTR];

    int bm = blockIdx.x * 128;
    int tid = threadIdx.x;
    int lane = tid & 31;
    int wid = tid >> 5;
    int warp_m = wid & 3;      // m offset 32*warp_m
    int warp_n = wid >> 2;     // n offset 32*warp_n

    int grow = tid >> 1;            // 0..127
    int gkoff = (tid & 1) * 8;      // 0 or 8

    float acc[2][4][4];
#pragma unroll
    for (int mi = 0; mi < 2; mi++)
#pragma unroll
        for (int ni = 0; ni < 4; ni++)
#pragma unroll
            for (int j = 0; j < 4; j++) acc[mi][ni][j] = 0.f;

    uint4 ra, rb;
    {
        int r = bm + grow;
        ra = make_uint4(0, 0, 0, 0);
        if (r < NN) ra = *(const uint4*)(g_h + (size_t)r * HID + gkoff);
        rb = make_uint4(0, 0, 0, 0);
        if (grow < 64) rb = *(const uint4*)(g_W2h + (size_t)grow * HID + gkoff);
    }

    for (int kt = 0; kt < K2TILES; kt++) {
        int buf = kt & 1;
        *(uint4*)&As[buf][grow][gkoff] = ra;
        if (grow < 64) *(uint4*)&Bs[buf][grow][gkoff] = rb;
        __syncthreads();

        if (kt + 1 < K2TILES) {
            int k0 = (kt + 1) * 16;
            int r = bm + grow;
            ra = make_uint4(0, 0, 0, 0);
            if (r < NN) ra = *(const uint4*)(g_h + (size_t)r * HID + k0 + gkoff);
            if (grow < 64) rb = *(const uint4*)(g_W2h + (size_t)grow * HID + k0 + gkoff);
        }

        int mg = lane >> 2;
        int tk = (lane & 3) * 2;
        unsigned afrag[2][4], bfrag[4][2];
#pragma unroll
        for (int mi = 0; mi < 2; mi++) {
            int m0 = warp_m * 32 + mi * 16 + mg;
            afrag[mi][0] = *(const unsigned*)&As[buf][m0][tk];
            afrag[mi][1] = *(const unsigned*)&As[buf][m0 + 8][tk];
            afrag[mi][2] = *(const unsigned*)&As[buf][m0][tk + 8];
            afrag[mi][3] = *(const unsigned*)&As[buf][m0 + 8][tk + 8];
        }
#pragma unroll
        for (int ni = 0; ni < 4; ni++) {
            int n0 = warp_n * 32 + ni * 8 + mg;
            bfrag[ni][0] = *(const unsigned*)&Bs[buf][n0][tk];
            bfrag[ni][1] = *(const unsigned*)&Bs[buf][n0][tk + 8];
        }
#pragma unroll
        for (int mi = 0; mi < 2; mi++)
#pragma unroll
            for (int ni = 0; ni < 4; ni++) {
                asm volatile(
                    "mma.sync.aligned.m16n8k16.row.col.f32.f16.f16.f32 "
                    "{%0,%1,%2,%3}, {%4,%5,%6,%7}, {%8,%9}, {%0,%1,%2,%3};"
                    : "+f"(acc[mi][ni][0]), "+f"(acc[mi][ni][1]),
                      "+f"(acc[mi][ni][2]), "+f"(acc[mi][ni][3])
                    : "r"(afrag[mi][0]), "r"(afrag[mi][1]),
                      "r"(afrag[mi][2]), "r"(afrag[mi][3]),
                      "r"(bfrag[ni][0]), "r"(bfrag[ni][1]));
            }
    }

    // epilogue: add folded bias, write fp32 out
    int mg = lane >> 2;
    int cq = (lane & 3) * 2;
#pragma unroll
    for (int mi = 0; mi < 2; mi++) {
        int r0 = bm + warp_m * 32 + mi * 16 + mg;
#pragma unroll
        for (int ni = 0; ni < 4; ni++) {
            int c = warp_n * 32 + ni * 8 + cq;
            float bb0 = g_b2p[c], bb1 = g_b2p[c + 1];
            if (r0 < NN)
                *(float2*)(out + (size_t)r0 * DOUT + c) =
                    make_float2(acc[mi][ni][0] + bb0, acc[mi][ni][1] + bb1);
            if (r0 + 8 < NN)
                *(float2*)(out + (size_t)(r0 + 8) * DOUT + c) =
                    make_float2(acc[mi][ni][2] + bb0, acc[mi][ni][3] + bb1);
        }
    }
}

// --------------------------------- launch ----------------------------------
extern "C" void kernel_launch(void* const* d_in, const int* in_sizes, int n_in,
                              void* d_out, int out_size) {
    const float* feat  = (const float*)d_in[0];
    const void*  ei    = d_in[1];
    const float* W1    = (const float*)d_in[2];
    const float* b1    = (const float*)d_in[3];
    const float* gamma = (const float*)d_in[4];
    const float* beta  = (const float*)d_in[5];
    const float* W2    = (const float*)d_in[6];
    const float* b2    = (const float*)d_in[7];
    float* out = (float*)d_out;
    float* norm_out = out + (size_t)NN * DOUT;   // [E+N] norm output section

    init_kernel<<<128, 512>>>((const unsigned int*)ei);
    convert_kernel<<<(EE + 255) / 256, 256>>>(ei);

    int nb = (NN + 1023) / 1024;   // 49
    scan_local<<<nb, 1024>>>(norm_out);
    scan_bsum<<<1, 32>>>(nb);
    scan_add<<<nb, 1024>>>();
    scatter_kernel<<<(EE + 255) / 256, 256>>>(ei, norm_out);

    copy_x0<<<(NN * DIN / 2 + 255) / 256, 256>>>(feat);
    w1t_kernel<<<dim3(DCAT / 32, HID / 32), dim3(32, 32)>>>(W1);

    for (int k = 0; k < KHOP; k++)
        prop_kernel<<<(NN * 32 + 255) / 256, 256>>>(k * DIN, (k + 1) * DIN);

    dim3 g1(HID / 128, (NN + 127) / 128);
    gemm1_fp16_kernel<<<g1, 256>>>(b1);

    finalize_kernel<<<1, 512>>>(W2, b2, gamma, beta);

    gemm2_fp16_kernel<<<(NN + 127) / 128, 256>>>(out);
}